// round 1
// baseline (speedup 1.0000x reference)
#include <cuda_runtime.h>

// FasterTensorProduct — bilinear factorization.
// out[b,n1,n2,k] = sum_c sh[b,n1,c] * Y[b,n2][k][c],  Y = x @ A_c (weight-derived).
//
// Shapes: in_ (4,1,128,272) f32, sh (4,128,1,4) f32, weight (13568,) f32.
// out (4,128,128,272) f32 = 17,825,792 elements.

#define IN_DIM 272
#define NROW   512   // B*N
#define NB     4
#define NN     128

// Weight sub-matrix offsets (row-major [a][b]):
#define W0E_OFF 0      // 96 x 64
#define W1O_OFF 6144   // 128 x 32
#define W1E_OFF 10240  // 80 x 32
#define W0O_OFF 12800  // 48 x 16

// Y scratch: [row][k] float4 (c innermost). 512*272*16B = 2.23 MB (L2-resident).
__device__ float4 g_Y[NROW * IN_DIM];

// ---------------------------------------------------------------------------
// Stage 1: per input row, compute Y[k][c].
// Block handles R=4 rows with 160 threads (threads grouped by output segment).
// ---------------------------------------------------------------------------
#define R1 4

__global__ __launch_bounds__(160) void tp_stage1(const float* __restrict__ in_,
                                                 const float* __restrict__ w)
{
    __shared__ float sx[R1][IN_DIM];
    const int r0 = blockIdx.x * R1;

    for (int idx = threadIdx.x; idx < R1 * IN_DIM; idx += blockDim.x)
        sx[idx / IN_DIM][idx % IN_DIM] = in_[r0 * IN_DIM + idx];
    __syncthreads();

    const int t = threadIdx.x;

    if (t < 64) {
        // ---- segment A: y0e channels, o = t (0..63) ----
        const int o = t;
        float a0[R1] = {}, a1[R1][3] = {};
        #pragma unroll 4
        for (int j = 0; j < 64; j++) {
            const float wv = w[W0E_OFF + j * 64 + o];
            #pragma unroll
            for (int r = 0; r < R1; r++) a0[r] += sx[r][j] * wv;
        }
        #pragma unroll 2
        for (int k = 0; k < 32; k++) {
            const float wv = w[W0E_OFF + (64 + k) * 64 + o];
            #pragma unroll
            for (int r = 0; r < R1; r++)
                #pragma unroll
                for (int d = 0; d < 3; d++)
                    a1[r][d] += sx[r][64 + 3 * k + d] * wv;
        }
        const float s  = 0.10206207262f;   // 1/sqrt(96)
        const float s3 = 0.05892556510f;   // 1/sqrt(96*3)
        #pragma unroll
        for (int r = 0; r < R1; r++)
            g_Y[(r0 + r) * IN_DIM + o] =
                make_float4(s * a0[r], s3 * a1[r][0], s3 * a1[r][1], s3 * a1[r][2]);
    }
    else if (t < 96) {
        // ---- segment B: y1o channels, o = t-64 (0..31) ----
        const int o = t - 64;
        float b0[R1] = {}, b1[R1][3] = {}, b2[R1][3] = {};
        #pragma unroll 4
        for (int j = 0; j < 64; j++) {
            const float wv = w[W1O_OFF + j * 32 + o];
            #pragma unroll
            for (int r = 0; r < R1; r++) b0[r] += sx[r][j] * wv;
        }
        #pragma unroll 2
        for (int k = 0; k < 32; k++) {
            const float wv = w[W1O_OFF + (64 + k) * 32 + o];
            #pragma unroll
            for (int r = 0; r < R1; r++)
                #pragma unroll
                for (int d = 0; d < 3; d++)
                    b1[r][d] += sx[r][64 + 3 * k + d] * wv;
        }
        #pragma unroll 2
        for (int k = 0; k < 32; k++) {
            const float wv = w[W1O_OFF + (96 + k) * 32 + o];
            #pragma unroll
            for (int r = 0; r < R1; r++)
                #pragma unroll
                for (int e = 0; e < 3; e++)
                    b2[r][e] += sx[r][160 + 3 * k + e] * wv;
        }
        const float s   = 0.08838834765f;  // 1/sqrt(128)
        const float si2 = 0.0625f;         // 1/sqrt(128*2) = 1/16
        #pragma unroll
        for (int r = 0; r < R1; r++) {
            #pragma unroll
            for (int c = 0; c < 3; c++) {
                float v[4];
                v[0]               =  s   * b1[r][c];
                v[1 + c]           =  s   * b0[r];
                v[1 + (c + 2) % 3] =  si2 * b2[r][(c + 1) % 3];
                v[1 + (c + 1) % 3] = -si2 * b2[r][(c + 2) % 3];
                g_Y[(r0 + r) * IN_DIM + 64 + 3 * o + c] =
                    make_float4(v[0], v[1], v[2], v[3]);
            }
        }
    }
    else if (t < 128) {
        // ---- segment C: y1e channels, o = t-96 (0..31) ----
        const int o = t - 96;
        float c0[R1][3] = {}, c1[R1][3] = {}, c2[R1] = {};
        #pragma unroll 2
        for (int k = 0; k < 32; k++) {
            const float wv = w[W1E_OFF + k * 32 + o];
            #pragma unroll
            for (int r = 0; r < R1; r++)
                #pragma unroll
                for (int e = 0; e < 3; e++)
                    c0[r][e] += sx[r][64 + 3 * k + e] * wv;
        }
        #pragma unroll 2
        for (int k = 0; k < 32; k++) {
            const float wv = w[W1E_OFF + (32 + k) * 32 + o];
            #pragma unroll
            for (int r = 0; r < R1; r++)
                #pragma unroll
                for (int d = 0; d < 3; d++)
                    c1[r][d] += sx[r][160 + 3 * k + d] * wv;
        }
        #pragma unroll 4
        for (int j = 0; j < 16; j++) {
            const float wv = w[W1E_OFF + (64 + j) * 32 + o];
            #pragma unroll
            for (int r = 0; r < R1; r++) c2[r] += sx[r][256 + j] * wv;
        }
        const float s   = 0.11180339887f;  // 1/sqrt(80)
        const float si2 = 0.07905694150f;  // 1/sqrt(160)
        #pragma unroll
        for (int r = 0; r < R1; r++) {
            #pragma unroll
            for (int c = 0; c < 3; c++) {
                float v[4];
                v[0]               =  s   * c1[r][c];
                v[1 + c]           =  s   * c2[r];
                v[1 + (c + 2) % 3] =  si2 * c0[r][(c + 1) % 3];
                v[1 + (c + 1) % 3] = -si2 * c0[r][(c + 2) % 3];
                g_Y[(r0 + r) * IN_DIM + 160 + 3 * o + c] =
                    make_float4(v[0], v[1], v[2], v[3]);
            }
        }
    }
    else if (t < 144) {
        // ---- segment D: y0o channels, o = t-128 (0..15) ----
        const int o = t - 128;
        float d0[R1][3] = {}, d1[R1] = {};
        #pragma unroll 2
        for (int k = 0; k < 32; k++) {
            const float wv = w[W0O_OFF + k * 16 + o];
            #pragma unroll
            for (int r = 0; r < R1; r++)
                #pragma unroll
                for (int d = 0; d < 3; d++)
                    d0[r][d] += sx[r][160 + 3 * k + d] * wv;
        }
        #pragma unroll 4
        for (int j = 0; j < 16; j++) {
            const float wv = w[W0O_OFF + (32 + j) * 16 + o];
            #pragma unroll
            for (int r = 0; r < R1; r++) d1[r] += sx[r][256 + j] * wv;
        }
        const float s  = 0.14433756730f;   // 1/sqrt(48)
        const float s3 = 0.08333333333f;   // 1/12
        #pragma unroll
        for (int r = 0; r < R1; r++)
            g_Y[(r0 + r) * IN_DIM + 256 + o] =
                make_float4(s * d1[r], s3 * d0[r][0], s3 * d0[r][1], s3 * d0[r][2]);
    }
}

// ---------------------------------------------------------------------------
// Stage 2: out[b,n1,n2,k] = dot4(sh[b,n1], Y[b,n2][k]).
// Grid (32 n2-tiles, 4 n1-tiles, 4 b); block 272 threads.
// Each thread owns one (k-float4, n2) slot, registers-resident Y, loops 32 n1.
// ---------------------------------------------------------------------------
#define T1 32

__global__ __launch_bounds__(272) void tp_stage2(const float* __restrict__ sh,
                                                 float* __restrict__ out)
{
    const int tid = threadIdx.x;
    const int kv  = tid % 68;     // float4 index within 272
    const int n2l = tid / 68;     // 0..3
    const int b   = blockIdx.z;
    const int n2  = blockIdx.x * 4 + n2l;
    const int n1b = blockIdx.y * T1;

    const int r = b * NN + n2;
    const float4* Yp = &g_Y[r * IN_DIM + kv * 4];
    const float4 y0 = Yp[0], y1 = Yp[1], y2 = Yp[2], y3 = Yp[3];

    const float4* shp = reinterpret_cast<const float4*>(sh) + (b * NN + n1b);
    float4* op = reinterpret_cast<float4*>(out)
               + ((size_t)(b * NN + n1b) * NN + n2) * (IN_DIM / 4) + kv;
    const size_t stride = (size_t)NN * (IN_DIM / 4);  // per-n1 float4 stride

    #pragma unroll 4
    for (int i = 0; i < T1; i++) {
        const float4 s = __ldg(&shp[i]);
        float4 o;
        o.x = s.x * y0.x + s.y * y0.y + s.z * y0.z + s.w * y0.w;
        o.y = s.x * y1.x + s.y * y1.y + s.z * y1.z + s.w * y1.w;
        o.z = s.x * y2.x + s.y * y2.y + s.z * y2.z + s.w * y2.w;
        o.w = s.x * y3.x + s.y * y3.y + s.z * y3.z + s.w * y3.w;
        op[i * stride] = o;
    }
}

extern "C" void kernel_launch(void* const* d_in, const int* in_sizes, int n_in,
                              void* d_out, int out_size)
{
    const float* in_ = (const float*)d_in[0];   // (4,1,128,272)
    const float* sh  = (const float*)d_in[1];   // (4,128,1,4)
    const float* w   = (const float*)d_in[2];   // (13568,)
    float* out = (float*)d_out;

    tp_stage1<<<NROW / R1, 160>>>(in_, w);
    tp_stage2<<<dim3(NN / 4, NN / T1, NB), 272>>>(sh, out);
}

// round 2
// speedup vs baseline: 1.1312x; 1.1312x over previous
#include <cuda_runtime.h>

// FasterTensorProduct — bilinear factorization.
// out[b,n1,n2,k] = sum_c sh[b,n1,c] * Y[b,n2][k][c],  Y = x @ A_c (weight-derived).

#define IN_DIM 272
#define NROW   512   // B*N
#define NB     4
#define NN     128

#define W0E_OFF 0      // 96 x 64
#define W1O_OFF 6144   // 128 x 32
#define W1E_OFF 10240  // 80 x 32
#define W0O_OFF 12800  // 48 x 16

// Y scratch: [row][k] float4 (c innermost). 512*272*16B = 2.23 MB (L2-resident).
__device__ float4 g_Y[NROW * IN_DIM];

// ---------------------------------------------------------------------------
// Stage 1: per input row, compute Y[k][c]. One row per block, 160 threads.
// ---------------------------------------------------------------------------
__global__ __launch_bounds__(160) void tp_stage1(const float* __restrict__ in_,
                                                 const float* __restrict__ w)
{
    __shared__ float sx[IN_DIM];
    const int r0 = blockIdx.x;

    for (int idx = threadIdx.x; idx < IN_DIM; idx += blockDim.x)
        sx[idx] = in_[r0 * IN_DIM + idx];
    __syncthreads();

    const int t = threadIdx.x;

    if (t < 64) {
        // ---- segment A: y0e channels, o = t (0..63) ----
        const int o = t;
        float a0 = 0.f, a1[3] = {};
        #pragma unroll 8
        for (int j = 0; j < 64; j++)
            a0 += sx[j] * w[W0E_OFF + j * 64 + o];
        #pragma unroll 4
        for (int k = 0; k < 32; k++) {
            const float wv = w[W0E_OFF + (64 + k) * 64 + o];
            #pragma unroll
            for (int d = 0; d < 3; d++) a1[d] += sx[64 + 3 * k + d] * wv;
        }
        const float s  = 0.10206207262f;   // 1/sqrt(96)
        const float s3 = 0.05892556510f;   // 1/sqrt(96*3)
        g_Y[r0 * IN_DIM + o] = make_float4(s * a0, s3 * a1[0], s3 * a1[1], s3 * a1[2]);
    }
    else if (t < 96) {
        // ---- segment B: y1o channels, o = t-64 (0..31) ----
        const int o = t - 64;
        float b0 = 0.f, b1[3] = {}, b2[3] = {};
        #pragma unroll 8
        for (int j = 0; j < 64; j++)
            b0 += sx[j] * w[W1O_OFF + j * 32 + o];
        #pragma unroll 4
        for (int k = 0; k < 32; k++) {
            const float wv = w[W1O_OFF + (64 + k) * 32 + o];
            #pragma unroll
            for (int d = 0; d < 3; d++) b1[d] += sx[64 + 3 * k + d] * wv;
        }
        #pragma unroll 4
        for (int k = 0; k < 32; k++) {
            const float wv = w[W1O_OFF + (96 + k) * 32 + o];
            #pragma unroll
            for (int e = 0; e < 3; e++) b2[e] += sx[160 + 3 * k + e] * wv;
        }
        const float s   = 0.08838834765f;  // 1/sqrt(128)
        const float si2 = 0.0625f;         // 1/sqrt(128*2)
        #pragma unroll
        for (int c = 0; c < 3; c++) {
            float v[4];
            v[0]               =  s   * b1[c];
            v[1 + c]           =  s   * b0;
            v[1 + (c + 2) % 3] =  si2 * b2[(c + 1) % 3];
            v[1 + (c + 1) % 3] = -si2 * b2[(c + 2) % 3];
            g_Y[r0 * IN_DIM + 64 + 3 * o + c] = make_float4(v[0], v[1], v[2], v[3]);
        }
    }
    else if (t < 128) {
        // ---- segment C: y1e channels, o = t-96 (0..31) ----
        const int o = t - 96;
        float c0[3] = {}, c1[3] = {}, c2 = 0.f;
        #pragma unroll 4
        for (int k = 0; k < 32; k++) {
            const float wv = w[W1E_OFF + k * 32 + o];
            #pragma unroll
            for (int e = 0; e < 3; e++) c0[e] += sx[64 + 3 * k + e] * wv;
        }
        #pragma unroll 4
        for (int k = 0; k < 32; k++) {
            const float wv = w[W1E_OFF + (32 + k) * 32 + o];
            #pragma unroll
            for (int d = 0; d < 3; d++) c1[d] += sx[160 + 3 * k + d] * wv;
        }
        #pragma unroll 8
        for (int j = 0; j < 16; j++)
            c2 += sx[256 + j] * w[W1E_OFF + (64 + j) * 32 + o];
        const float s   = 0.11180339887f;  // 1/sqrt(80)
        const float si2 = 0.07905694150f;  // 1/sqrt(160)
        #pragma unroll
        for (int c = 0; c < 3; c++) {
            float v[4];
            v[0]               =  s   * c1[c];
            v[1 + c]           =  s   * c2;
            v[1 + (c + 2) % 3] =  si2 * c0[(c + 1) % 3];
            v[1 + (c + 1) % 3] = -si2 * c0[(c + 2) % 3];
            g_Y[r0 * IN_DIM + 160 + 3 * o + c] = make_float4(v[0], v[1], v[2], v[3]);
        }
    }
    else if (t < 144) {
        // ---- segment D: y0o channels, o = t-128 (0..15) ----
        const int o = t - 128;
        float d0[3] = {}, d1 = 0.f;
        #pragma unroll 4
        for (int k = 0; k < 32; k++) {
            const float wv = w[W0O_OFF + k * 16 + o];
            #pragma unroll
            for (int d = 0; d < 3; d++) d0[d] += sx[160 + 3 * k + d] * wv;
        }
        #pragma unroll 8
        for (int j = 0; j < 16; j++)
            d1 += sx[256 + j] * w[W0O_OFF + (32 + j) * 16 + o];
        const float s  = 0.14433756730f;   // 1/sqrt(48)
        const float s3 = 0.08333333333f;   // 1/12
        g_Y[r0 * IN_DIM + 256 + o] = make_float4(s * d1, s3 * d0[0], s3 * d0[1], s3 * d0[2]);
    }
}

// ---------------------------------------------------------------------------
// Stage 2: out[b,n1,n2,k] = dot4(sh[b,n1], Y[b,n2][k]).
// Grid (32 n2-tiles, 16 n1-tiles, 4 b); block 272 threads.
// Each thread owns one (k-float4, n2) slot, registers-resident Y, loops 8 n1.
// ---------------------------------------------------------------------------
#define T1 8

__global__ __launch_bounds__(272) void tp_stage2(const float* __restrict__ sh,
                                                 float* __restrict__ out)
{
    const int tid = threadIdx.x;
    const int kv  = tid % 68;     // float4 index within 272
    const int n2l = tid / 68;     // 0..3
    const int b   = blockIdx.z;
    const int n2  = blockIdx.x * 4 + n2l;
    const int n1b = blockIdx.y * T1;

    const int r = b * NN + n2;
    const float4* Yp = &g_Y[r * IN_DIM + kv * 4];
    const float4 y0 = Yp[0], y1 = Yp[1], y2 = Yp[2], y3 = Yp[3];

    const float4* shp = reinterpret_cast<const float4*>(sh) + (b * NN + n1b);
    float4* op = reinterpret_cast<float4*>(out)
               + ((size_t)(b * NN + n1b) * NN + n2) * (IN_DIM / 4) + kv;
    const size_t stride = (size_t)NN * (IN_DIM / 4);  // per-n1 float4 stride

    #pragma unroll
    for (int i = 0; i < T1; i++) {
        const float4 s = __ldg(&shp[i]);
        float4 o;
        o.x = s.x * y0.x + s.y * y0.y + s.z * y0.z + s.w * y0.w;
        o.y = s.x * y1.x + s.y * y1.y + s.z * y1.z + s.w * y1.w;
        o.z = s.x * y2.x + s.y * y2.y + s.z * y2.z + s.w * y2.w;
        o.w = s.x * y3.x + s.y * y3.y + s.z * y3.z + s.w * y3.w;
        op[i * stride] = o;
    }
}

extern "C" void kernel_launch(void* const* d_in, const int* in_sizes, int n_in,
                              void* d_out, int out_size)
{
    const float* in_ = (const float*)d_in[0];   // (4,1,128,272)
    const float* sh  = (const float*)d_in[1];   // (4,128,1,4)
    const float* w   = (const float*)d_in[2];   // (13568,)
    float* out = (float*)d_out;

    tp_stage1<<<NROW, 160>>>(in_, w);
    tp_stage2<<<dim3(NN / 4, NN / T1, NB), 272>>>(sh, out);
}

// round 4
// speedup vs baseline: 1.3117x; 1.1596x over previous
#include <cuda_runtime.h>

// FasterTensorProduct — bilinear factorization.
// out[b,n1,n2,k] = sum_c sh[b,n1,c] * Y[b,n2][k][c],  Y = x @ A_c (weight-derived).

#define IN_DIM 272
#define NROW   512   // B*N
#define NB     4
#define NN     128

#define W0E_OFF 0      // 96 x 64
#define W1O_OFF 6144   // 128 x 32
#define W1E_OFF 10240  // 80 x 32
#define W0O_OFF 12800  // 48 x 16

// Y scratch: [row][k] float4 (c innermost). 512*272*16B = 2.23 MB (L2-resident).
__device__ float4 g_Y[NROW * IN_DIM];

// ---------------------------------------------------------------------------
// Stage 1: per input row, compute Y[k][c]. One row per block, 320 threads:
// two halves (t<160 / t>=160) each reduce half the contraction range, then
// combine through shared memory. Halves the serial FMA chains vs 160-thread.
// ---------------------------------------------------------------------------
// Partial layout (floats): A[2][64][4] | B[2][32][7] | C[2][32][7] | D[2][16][4]
#define PA 0
#define PB 512
#define PC 960
#define PD 1408
#define PTOT 1536

__global__ __launch_bounds__(320) void tp_stage1(const float* __restrict__ in_,
                                                 const float* __restrict__ w)
{
    __shared__ float sx[IN_DIM];
    __shared__ float part[PTOT];
    const int r0 = blockIdx.x;
    const int t  = threadIdx.x;

    for (int idx = t; idx < IN_DIM; idx += blockDim.x)
        sx[idx] = in_[r0 * IN_DIM + idx];
    __syncthreads();

    const int half = (t >= 160) ? 1 : 0;
    const int u    = t - 160 * half;

    if (u < 64) {
        // ---- segment A partials: o = u ----
        const int o = u;
        const int j0 = half * 32, k0 = half * 16;
        float a0 = 0.f, a1[3] = {};
        #pragma unroll 8
        for (int j = j0; j < j0 + 32; j++)
            a0 += sx[j] * w[W0E_OFF + j * 64 + o];
        #pragma unroll 4
        for (int k = k0; k < k0 + 16; k++) {
            const float wv = w[W0E_OFF + (64 + k) * 64 + o];
            #pragma unroll
            for (int d = 0; d < 3; d++) a1[d] += sx[64 + 3 * k + d] * wv;
        }
        float* p = &part[PA + half * 256 + o * 4];
        p[0] = a0; p[1] = a1[0]; p[2] = a1[1]; p[3] = a1[2];
    }
    else if (u < 96) {
        // ---- segment B partials: o = u-64 ----
        const int o = u - 64;
        const int j0 = half * 32, k0 = half * 16;
        float b0 = 0.f, b1[3] = {}, b2[3] = {};
        #pragma unroll 8
        for (int j = j0; j < j0 + 32; j++)
            b0 += sx[j] * w[W1O_OFF + j * 32 + o];
        #pragma unroll 4
        for (int k = k0; k < k0 + 16; k++) {
            const float wv = w[W1O_OFF + (64 + k) * 32 + o];
            #pragma unroll
            for (int d = 0; d < 3; d++) b1[d] += sx[64 + 3 * k + d] * wv;
        }
        #pragma unroll 4
        for (int k = k0; k < k0 + 16; k++) {
            const float wv = w[W1O_OFF + (96 + k) * 32 + o];
            #pragma unroll
            for (int e = 0; e < 3; e++) b2[e] += sx[160 + 3 * k + e] * wv;
        }
        float* p = &part[PB + half * 224 + o * 7];
        p[0] = b0;
        p[1] = b1[0]; p[2] = b1[1]; p[3] = b1[2];
        p[4] = b2[0]; p[5] = b2[1]; p[6] = b2[2];
    }
    else if (u < 128) {
        // ---- segment C partials: o = u-96 ----
        const int o = u - 96;
        const int k0 = half * 16, j0 = half * 8;
        float c0[3] = {}, c1[3] = {}, c2 = 0.f;
        #pragma unroll 4
        for (int k = k0; k < k0 + 16; k++) {
            const float wv = w[W1E_OFF + k * 32 + o];
            #pragma unroll
            for (int e = 0; e < 3; e++) c0[e] += sx[64 + 3 * k + e] * wv;
        }
        #pragma unroll 4
        for (int k = k0; k < k0 + 16; k++) {
            const float wv = w[W1E_OFF + (32 + k) * 32 + o];
            #pragma unroll
            for (int d = 0; d < 3; d++) c1[d] += sx[160 + 3 * k + d] * wv;
        }
        #pragma unroll 8
        for (int j = j0; j < j0 + 8; j++)
            c2 += sx[256 + j] * w[W1E_OFF + (64 + j) * 32 + o];
        float* p = &part[PC + half * 224 + o * 7];
        p[0] = c2;
        p[1] = c0[0]; p[2] = c0[1]; p[3] = c0[2];
        p[4] = c1[0]; p[5] = c1[1]; p[6] = c1[2];
    }
    else if (u < 144) {
        // ---- segment D partials: o = u-128 ----
        const int o = u - 128;
        const int k0 = half * 16, j0 = half * 8;
        float d0[3] = {}, d1 = 0.f;
        #pragma unroll 4
        for (int k = k0; k < k0 + 16; k++) {
            const float wv = w[W0O_OFF + k * 16 + o];
            #pragma unroll
            for (int d = 0; d < 3; d++) d0[d] += sx[160 + 3 * k + d] * wv;
        }
        #pragma unroll 8
        for (int j = j0; j < j0 + 8; j++)
            d1 += sx[256 + j] * w[W0O_OFF + (32 + j) * 16 + o];
        float* p = &part[PD + half * 64 + o * 4];
        p[0] = d1; p[1] = d0[0]; p[2] = d0[1]; p[3] = d0[2];
    }
    __syncthreads();

    if (half) return;

    if (u < 64) {
        const int o = u;
        const float* p0 = &part[PA + o * 4];
        const float* p1 = &part[PA + 256 + o * 4];
        const float a0 = p0[0] + p1[0];
        const float a1x = p0[1] + p1[1], a1y = p0[2] + p1[2], a1z = p0[3] + p1[3];
        const float s  = 0.10206207262f;   // 1/sqrt(96)
        const float s3 = 0.05892556510f;   // 1/sqrt(96*3)
        g_Y[r0 * IN_DIM + o] = make_float4(s * a0, s3 * a1x, s3 * a1y, s3 * a1z);
    }
    else if (u < 96) {
        const int o = u - 64;
        const float* p0 = &part[PB + o * 7];
        const float* p1 = &part[PB + 224 + o * 7];
        const float b0 = p0[0] + p1[0];
        float b1[3], b2[3];
        #pragma unroll
        for (int d = 0; d < 3; d++) { b1[d] = p0[1 + d] + p1[1 + d]; b2[d] = p0[4 + d] + p1[4 + d]; }
        const float s   = 0.08838834765f;  // 1/sqrt(128)
        const float si2 = 0.0625f;         // 1/sqrt(128*2)
        #pragma unroll
        for (int c = 0; c < 3; c++) {
            float v[4];
            v[0]               =  s   * b1[c];
            v[1 + c]           =  s   * b0;
            v[1 + (c + 2) % 3] =  si2 * b2[(c + 1) % 3];
            v[1 + (c + 1) % 3] = -si2 * b2[(c + 2) % 3];
            g_Y[r0 * IN_DIM + 64 + 3 * o + c] = make_float4(v[0], v[1], v[2], v[3]);
        }
    }
    else if (u < 128) {
        const int o = u - 96;
        const float* p0 = &part[PC + o * 7];
        const float* p1 = &part[PC + 224 + o * 7];
        const float c2 = p0[0] + p1[0];
        float c0[3], c1[3];
        #pragma unroll
        for (int d = 0; d < 3; d++) { c0[d] = p0[1 + d] + p1[1 + d]; c1[d] = p0[4 + d] + p1[4 + d]; }
        const float s   = 0.11180339887f;  // 1/sqrt(80)
        const float si2 = 0.07905694150f;  // 1/sqrt(160)
        #pragma unroll
        for (int c = 0; c < 3; c++) {
            float v[4];
            v[0]               =  s   * c1[c];
            v[1 + c]           =  s   * c2;
            v[1 + (c + 2) % 3] =  si2 * c0[(c + 1) % 3];
            v[1 + (c + 1) % 3] = -si2 * c0[(c + 2) % 3];
            g_Y[r0 * IN_DIM + 160 + 3 * o + c] = make_float4(v[0], v[1], v[2], v[3]);
        }
    }
    else if (u < 144) {
        const int o = u - 128;
        const float* p0 = &part[PD + o * 4];
        const float* p1 = &part[PD + 64 + o * 4];
        const float d1 = p0[0] + p1[0];
        const float s  = 0.14433756730f;   // 1/sqrt(48)
        const float s3 = 0.08333333333f;   // 1/12
        g_Y[r0 * IN_DIM + 256 + o] =
            make_float4(s * d1, s3 * (p0[1] + p1[1]), s3 * (p0[2] + p1[2]), s3 * (p0[3] + p1[3]));
    }
}

// ---------------------------------------------------------------------------
// Stage 2: out[b,n1,n2,k] = dot4(sh[b,n1], Y[b,n2][k]).
// 256-thread blocks, flat j = n2*68+kv addressing (perfect store coalescing),
// sh tile staged in smem, 8 n1 per thread fully unrolled.
// Grid (34, 16, 4).
// ---------------------------------------------------------------------------
#define T1 8

__global__ __launch_bounds__(256, 6) void tp_stage2(const float* __restrict__ sh,
                                                    float* __restrict__ out)
{
    __shared__ float4 ssh[T1];
    const int tid = threadIdx.x;
    const int b   = blockIdx.z;
    const int n1b = blockIdx.y * T1;
    const int j   = blockIdx.x * 256 + tid;   // n2*68 + kv, 0..8703

    if (tid < T1)
        ssh[tid] = reinterpret_cast<const float4*>(sh)[b * NN + n1b + tid];
    __syncthreads();

    const int n2 = j / 68;
    const int kv = j - n2 * 68;

    const float4* Yp = &g_Y[(b * NN + n2) * IN_DIM + kv * 4];
    const float4 y0 = Yp[0], y1 = Yp[1], y2 = Yp[2], y3 = Yp[3];

    float4* op = reinterpret_cast<float4*>(out)
               + (size_t)(b * NN + n1b) * (NN * (IN_DIM / 4)) + j;
    const size_t stride = NN * (IN_DIM / 4);  // 8704 float4 per n1

    #pragma unroll
    for (int i = 0; i < T1; i++) {
        const float4 s = ssh[i];
        float4 o;
        o.x = s.x * y0.x + s.y * y0.y + s.z * y0.z + s.w * y0.w;
        o.y = s.x * y1.x + s.y * y1.y + s.z * y1.z + s.w * y1.w;
        o.z = s.x * y2.x + s.y * y2.y + s.z * y2.z + s.w * y2.w;
        o.w = s.x * y3.x + s.y * y3.y + s.z * y3.z + s.w * y3.w;
        op[i * stride] = o;
    }
}

extern "C" void kernel_launch(void* const* d_in, const int* in_sizes, int n_in,
                              void* d_out, int out_size)
{
    const float* in_ = (const float*)d_in[0];   // (4,1,128,272)
    const float* sh  = (const float*)d_in[1];   // (4,128,1,4)
    const float* w   = (const float*)d_in[2];   // (13568,)
    float* out = (float*)d_out;

    tp_stage1<<<NROW, 320>>>(in_, w);
    tp_stage2<<<dim3(34, NN / T1, NB), 256>>>(sh, out);
}